// round 11
// baseline (speedup 1.0000x reference)
#include <cuda_runtime.h>
#include <math.h>

typedef unsigned long long ull;

#define Nn 64
#define Tt 800
#define Hh 512
#define H2 1024
#define G3 3072
#define Oo 80
#define Rr 2
#define ASPLIT 25
#define TSLICE 32

// ---------------- scratch (device globals; no allocation) ----------------
__device__ float g_pre1[Nn * H2];
__device__ float g_dec_proj[Nn * H2];
__device__ float g_dec_in[Nn * 2 * H2];
__device__ float g_residual[Nn * H2];
__device__ float g_pgi[16 * Nn * G3];
__device__ float g_pha[8 * Nn * G3];
__device__ float g_ph1[8 * Nn * G3];
__device__ float g_ph2[8 * Nn * G3];
__device__ float g_psc[16 * Nn * H2];
__device__ float g_ppx[16 * Nn * H2];
__device__ float g_pvec[ASPLIT * Nn * H2];
__device__ float g_psum[ASPLIT * Nn];

// ---------------- batched split-K skinny GEMM (v4) ---------------------------
// Tile 64 rows x 64 cols; thread = 4 rows x 4 strided cols, f32x2 over k.
// W chunks double-buffered in smem (1 bar/chunk, reg-prefetch) for KC<=80;
// classic 2-bar path for KC=128 (smem budget). Optional fused split-K reduce
// (+bias+relu) of the X operand during staging.
struct GP {
    const float* X; const float* W; float* P; const float* bias;
    const float* xbias;
    int ldx; int K; int SK; int M; int cb; int fuse;  // fuse: 2 = bias+relu direct (SK==1)
    int xsk; int xrelu;
};

__device__ __forceinline__ void ffma2(ull& d, ull a, ull b)
{
    asm("fma.rn.f32x2 %0, %1, %2, %0;" : "+l"(d) : "l"(a), "l"(b));
}

__device__ __forceinline__ float fast_tanh(float x)
{
    float y;
    asm("tanh.approx.f32 %0, %1;" : "=f"(y) : "f"(x));
    return y;
}

template<int KC>
__device__ __forceinline__ void gemm_tile(const GP& p, int colb, int sp, char* raw)
{
    constexpr int  LDSX = (KC == 128) ? 132 : (KC + 4);
    constexpr bool PP   = (KC <= 80);
    constexpr int  WBUF = 64 * 36;

    float* sx = (float*)raw;
    float* ws = sx + 64 * LDSX;

    const int kbeg = sp * KC;
    const int tid  = threadIdx.x;

    {   // stage X[0:64][kbeg:kbeg+KC] (optionally summing xsk partial slices)
        const int r = tid >> 2, q = (tid & 3) * 4;
        float* sr = sx + r * LDSX;
        const float* xp = p.X + (size_t)r * p.ldx + kbeg + q;
        if (p.xsk == 1) {
#pragma unroll
            for (int kk = 0; kk < KC; kk += 16)
                *(float4*)&sr[kk + q] = *(const float4*)&xp[kk];
        } else {
            const size_t ss = (size_t)64 * p.ldx;
#pragma unroll
            for (int kk = 0; kk < KC; kk += 16) {
                float4 a = *(const float4*)&p.xbias[kbeg + kk + q];
                for (int s2 = 0; s2 < p.xsk; s2++) {
                    float4 v = *(const float4*)&xp[(size_t)s2 * ss + kk];
                    a.x += v.x; a.y += v.y; a.z += v.z; a.w += v.w;
                }
                if (p.xrelu) {
                    a.x = fmaxf(a.x, 0.f); a.y = fmaxf(a.y, 0.f);
                    a.z = fmaxf(a.z, 0.f); a.w = fmaxf(a.w, 0.f);
                }
                *(float4*)&sr[kk + q] = a;
            }
        }
    }

    // W loader mapping: thread covers (wcol, wcol+32) x 16B segment wseg
    const int wcol = tid >> 3;
    const int wseg = (tid & 7) * 4;
    int gc0 = colb * 64 + wcol;      if (gc0 >= p.M) gc0 = 0;
    int gc1 = colb * 64 + wcol + 32; if (gc1 >= p.M) gc1 = 0;
    const float* wg0 = p.W + (size_t)gc0 * p.K + kbeg + wseg;
    const float* wg1 = p.W + (size_t)gc1 * p.K + kbeg + wseg;

    constexpr int CS0 = KC < 32 ? KC : 32;
    float4 pf0 = make_float4(0.f, 0.f, 0.f, 0.f), pf1 = pf0;
    if (wseg < CS0) { pf0 = *(const float4*)wg0; pf1 = *(const float4*)wg1; }

    ull acc[4][4];
#pragma unroll
    for (int cc = 0; cc < 4; cc++)
#pragma unroll
        for (int r = 0; r < 4; r++) acc[cc][r] = 0ull;

    const int cg    = tid & 15;          // cols {cg, cg+16, cg+32, cg+48}
    const int rbase = (tid >> 4) * 4;    // rows rbase..rbase+3

    constexpr int NCH = (KC + 31) / 32;
#pragma unroll
    for (int ch = 0; ch < NCH; ch++) {
        const int k0 = ch * 32;
        const int cs = (KC - k0) < 32 ? (KC - k0) : 32;
        float* wb = PP ? (ws + (ch & 1) * WBUF) : ws;
        if (!PP) __syncthreads();
        *(float4*)&wb[wcol * 36 + wseg]        = pf0;
        *(float4*)&wb[(wcol + 32) * 36 + wseg] = pf1;
        __syncthreads();
        if (ch + 1 < NCH) {
            const int nk = (ch + 1) * 32;
            const int cs2 = (KC - nk) < 32 ? (KC - nk) : 32;
            if (wseg < cs2) {
                pf0 = *(const float4*)(wg0 + nk);
                pf1 = *(const float4*)(wg1 + nk);
            }
        }
        const float* xb = sx + rbase * LDSX + k0;
        const int nkp = cs >> 2;
#pragma unroll
        for (int kp = 0; kp < 8; kp++) {
            if (kp < nkp) {
                ulonglong2 xv[4], wv[4];
#pragma unroll
                for (int r = 0; r < 4; r++)
                    xv[r] = *(const ulonglong2*)(xb + r * LDSX + kp * 4);
#pragma unroll
                for (int cc = 0; cc < 4; cc++)
                    wv[cc] = *(const ulonglong2*)(wb + (cg + 16 * cc) * 36 + kp * 4);
#pragma unroll
                for (int cc = 0; cc < 4; cc++)
#pragma unroll
                    for (int r = 0; r < 4; r++) {
                        ffma2(acc[cc][r], xv[r].x, wv[cc].x);
                        ffma2(acc[cc][r], xv[r].y, wv[cc].y);
                    }
            }
        }
    }

    // epilogue: horizontal add + store (col-guarded)
#pragma unroll
    for (int cc = 0; cc < 4; cc++) {
        const int col = colb * 64 + cg + 16 * cc;
        if (col < p.M) {
#pragma unroll
            for (int r = 0; r < 4; r++) {
                float v = __uint_as_float((unsigned)(acc[cc][r] & 0xffffffffull)) +
                          __uint_as_float((unsigned)(acc[cc][r] >> 32));
                if (p.fuse) {
                    v += p.bias[col];
                    if (p.fuse == 2) v = fmaxf(v, 0.f);
                    p.P[(size_t)(rbase + r) * p.M + col] = v;
                } else {
                    p.P[(size_t)(sp * 64 + rbase + r) * p.M + col] = v;
                }
            }
        }
    }
}

__global__ void __launch_bounds__(256, 2) gemm_sk(GP p0, GP p1, GP p2, GP p3,
                                                  int n0, int n1, int n2)
{
    __shared__ __align__(16) char raw[43008];
    GP p; int lb;
    {
        const int bid = blockIdx.x;
        if (bid < n0)      { p = p0; lb = bid; }
        else if (bid < n1) { p = p1; lb = bid - n0; }
        else if (bid < n2) { p = p2; lb = bid - n1; }
        else               { p = p3; lb = bid - n2; }
    }
    const int colb = lb % p.cb;
    const int sp   = lb / p.cb;
    const int kc   = p.K / p.SK;          // 64, 80, or 128

    if (kc == 64)       gemm_tile<64>(p, colb, sp, raw);
    else if (kc == 128) gemm_tile<128>(p, colb, sp, raw);
    else                gemm_tile<80>(p, colb, sp, raw);
}

// ---------------- standalone partial reduce: out = sum(P) + bias (opt relu) ----------------
__global__ void reduce_k(const float* __restrict__ P, float* __restrict__ out,
                         const float* __restrict__ bias, int M, int SK, int relu)
{
    const int idx = blockIdx.x * 256 + threadIdx.x;
    const int r = idx / M, col = idx % M;
    float s = bias[col];
    for (int sp = 0; sp < SK; sp++) s += P[((size_t)(sp * 64 + r)) * M + col];
    if (relu) s = fmaxf(s, 0.f);
    out[(size_t)r * M + col] = s;
}

// ---------------- GRU combine with fused split-K reduce ----------------
__global__ void gru_k(const float* __restrict__ giP, int skGi,
                      const float* __restrict__ ghP, int skGh,
                      const float* __restrict__ bih, const float* __restrict__ bhh,
                      const float* __restrict__ hprev,
                      float* __restrict__ hout, float* __restrict__ hout2,
                      const float* __restrict__ scP, int skSc,
                      const float* __restrict__ b_sc,
                      const float* __restrict__ resin, float* __restrict__ resout)
{
    const int idx = blockIdx.x * 256 + threadIdx.x;    // 0..65535
    const int n = idx >> 10, h = idx & (H2 - 1);
    float ir = bih[h], iz = bih[h + H2], inn = bih[h + 2 * H2];
    for (int sp = 0; sp < skGi; sp++) {
        const size_t b = ((size_t)(sp * 64 + n)) * G3 + h;
        ir += giP[b]; iz += giP[b + H2]; inn += giP[b + 2 * H2];
    }
    float hr = bhh[h], hz = bhh[h + H2], hn = bhh[h + 2 * H2];
    for (int sp = 0; sp < skGh; sp++) {
        const size_t b = ((size_t)(sp * 64 + n)) * G3 + h;
        hr += ghP[b]; hz += ghP[b + H2]; hn += ghP[b + 2 * H2];
    }
    const float r  = 1.f / (1.f + __expf(-(ir + hr)));
    const float z  = 1.f / (1.f + __expf(-(iz + hz)));
    const float nn = fast_tanh(inn + r * hn);
    const float hp = hprev[(size_t)n * H2 + h];
    const float hv = (1.f - z) * nn + z * hp;
    hout[(size_t)n * H2 + h] = hv;
    if (hout2) hout2[(size_t)n * 2 * H2 + H2 + h] = hv;
    if (scP) {
        float rv = b_sc[h];
        for (int sp = 0; sp < skSc; sp++)
            rv += scP[((size_t)(sp * 64 + n)) * H2 + h];
        resout[(size_t)n * H2 + h] = rv + hv;
    } else if (resin) {
        resout[(size_t)n * H2 + h] = resin[(size_t)n * H2 + h] + hv;
    }
}

// ---------------- fused attention: scores + unnormalized weighted sum ----------------
__global__ void attn_fused_k(const float* __restrict__ enc,
                             const float* __restrict__ attW,
                             const float* __restrict__ dec_proj,
                             const float* __restrict__ Wattn,
                             const float* __restrict__ b_attn,
                             const int* __restrict__ lengths,
                             float* __restrict__ pvec,
                             float* __restrict__ psum)
{
    __shared__ float dp[H2];
    __shared__ float wa[H2];
    __shared__ float sc[TSLICE];
    __shared__ float wsum[8];
    const int n = blockIdx.y, sp = blockIdx.x;
    const int tid = threadIdx.x;
    {
        const int h = tid * 4;
        *(float4*)&dp[h] = *(const float4*)&dec_proj[(size_t)n * H2 + h];
        *(float4*)&wa[h] = *(const float4*)&Wattn[h];
    }
    const int t0  = sp * TSLICE;
    const int len = lengths[n];
    int eff = len - t0;
    if (eff > TSLICE) eff = TSLICE;
    if (eff < 0) eff = 0;
    __syncthreads();

    // phase 1: scores (warp per timestep), HW tanh
    const int warp = tid >> 5, lane = tid & 31;
    float wls = 0.f;
    for (int tl = warp; tl < eff; tl += 8) {
        const float* a = attW + ((size_t)n * Tt + t0 + tl) * H2;
        float s = 0.f;
#pragma unroll
        for (int i = 0; i < 8; i++) {
            const int h = i * 128 + lane * 4;
            float4 v = *(const float4*)&a[h];
            s += fast_tanh(v.x + dp[h + 0]) * wa[h + 0];
            s += fast_tanh(v.y + dp[h + 1]) * wa[h + 1];
            s += fast_tanh(v.z + dp[h + 2]) * wa[h + 2];
            s += fast_tanh(v.w + dp[h + 3]) * wa[h + 3];
        }
#pragma unroll
        for (int o = 16; o > 0; o >>= 1) s += __shfl_xor_sync(0xffffffffu, s, o);
        s = __expf(s + b_attn[0]);
        if (lane == 0) sc[tl] = s;
        wls += s;
    }
    if (lane == 0) wsum[warp] = wls;
    __syncthreads();

    if (tid == 0) {
        float tot = 0.f;
#pragma unroll
        for (int w = 0; w < 8; w++) tot += wsum[w];
        psum[(size_t)sp * Nn + n] = tot;
    }

    // phase 2: unnormalized weighted sum over this slice
    const int h = tid * 4;
    float4 acc = make_float4(0.f, 0.f, 0.f, 0.f);
    const float* ep = enc + ((size_t)n * Tt + t0) * H2 + h;
#pragma unroll 2
    for (int tl = 0; tl < eff; tl++) {
        const float w = sc[tl];
        float4 v = *(const float4*)(ep + (size_t)tl * H2);
        acc.x = fmaf(w, v.x, acc.x);
        acc.y = fmaf(w, v.y, acc.y);
        acc.z = fmaf(w, v.z, acc.z);
        acc.w = fmaf(w, v.w, acc.w);
    }
    *(float4*)&pvec[((size_t)sp * Nn + n) * H2 + h] = acc;
}

// ---------------- attention final reduce: normalize + write dec_in[:, :H2] ----------------
__global__ void attn_reduce2_k(const float* __restrict__ pvec,
                               const float* __restrict__ psum,
                               float* __restrict__ dec_in)
{
    const int n = blockIdx.x;
    __shared__ float ps[ASPLIT];
    if (threadIdx.x < ASPLIT) ps[threadIdx.x] = psum[(size_t)threadIdx.x * Nn + n];
    __syncthreads();
    float den = 0.f;
#pragma unroll
    for (int sp = 0; sp < ASPLIT; sp++) den += ps[sp];
    const float inv = 1.f / fmaxf(den, 1e-12f);
    const int h = threadIdx.x * 4;
    float4 acc = make_float4(0.f, 0.f, 0.f, 0.f);
#pragma unroll
    for (int sp = 0; sp < ASPLIT; sp++) {
        float4 v = *(const float4*)&pvec[((size_t)sp * Nn + n) * H2 + h];
        acc.x += v.x; acc.y += v.y; acc.z += v.z; acc.w += v.w;
    }
    acc.x *= inv; acc.y *= inv; acc.z *= inv; acc.w *= inv;
    *(float4*)&dec_in[(size_t)n * 2 * H2 + h] = acc;
}

// ---------------- host-side orchestration ----------------
static inline GP mkgp(const float* X, int ldx, const float* W, float* P,
                      int K, int SK, int M, const float* bias = nullptr, int fuse = 0,
                      int xsk = 1, const float* xbias = nullptr, int xrelu = 0)
{
    GP g; g.X = X; g.ldx = ldx; g.W = W; g.P = P; g.bias = bias; g.xbias = xbias;
    g.K = K; g.SK = SK; g.M = M; g.cb = (M + 63) / 64; g.fuse = fuse;
    g.xsk = xsk; g.xrelu = xrelu; return g;
}
static inline int nblk(const GP& g) { return g.cb * g.SK; }

static inline void launch1(const GP& a, cudaStream_t st = 0) {
    int n = nblk(a);
    gemm_sk<<<n, 256, 0, st>>>(a, a, a, a, n, n, n);
}
static inline void launch2(const GP& a, const GP& b, cudaStream_t st = 0) {
    int na = nblk(a), nb = nblk(b);
    gemm_sk<<<na + nb, 256, 0, st>>>(a, b, b, b, na, na + nb, na + nb);
}
static inline void launch3(const GP& a, const GP& b, const GP& c, cudaStream_t st = 0) {
    int na = nblk(a), nb = nblk(b), nc = nblk(c);
    gemm_sk<<<na + nb + nc, 256, 0, st>>>(a, b, c, c, na, na + nb, na + nb + nc);
}

extern "C" void kernel_launch(void* const* d_in, const int* in_sizes, int n_in,
                              void* d_out, int out_size)
{
    const float* input_enc      = (const float*)d_in[0];
    const float* input_attW_enc = (const float*)d_in[1];
    const float* input_dec      = (const float*)d_in[2];
    const int*   lengths_enc    = (const int*)  d_in[3];
    const float* hidden_att     = (const float*)d_in[4];
    const float* hidden_dec1    = (const float*)d_in[5];
    const float* hidden_dec2    = (const float*)d_in[6];
    const float* W_pre1 = (const float*)d_in[7];
    const float* b_pre1 = (const float*)d_in[8];
    const float* W_pre2 = (const float*)d_in[9];
    const float* b_pre2 = (const float*)d_in[10];
    const float* Wih_att = (const float*)d_in[11];
    const float* Whh_att = (const float*)d_in[12];
    const float* bih_att = (const float*)d_in[13];
    const float* bhh_att = (const float*)d_in[14];
    const float* W_ld   = (const float*)d_in[15];
    const float* b_ld   = (const float*)d_in[16];
    const float* W_attn = (const float*)d_in[17];
    const float* b_attn = (const float*)d_in[18];
    const float* W_sc   = (const float*)d_in[19];
    const float* b_sc   = (const float*)d_in[20];
    const float* Wih_d1 = (const float*)d_in[21];
    const float* Whh_d1 = (const float*)d_in[22];
    const float* bih_d1 = (const float*)d_in[23];
    const float* bhh_d1 = (const float*)d_in[24];
    const float* Wih_d2 = (const float*)d_in[25];
    const float* Whh_d2 = (const float*)d_in[26];
    const float* bih_d2 = (const float*)d_in[27];
    const float* bhh_d2 = (const float*)d_in[28];
    const float* W_out  = (const float*)d_in[29];
    const float* b_out  = (const float*)d_in[30];

    float *pre1, *dec_proj, *dec_in, *residual;
    float *pgi, *pha, *ph1, *ph2, *psc, *ppx, *pvec, *psum;
    cudaGetSymbolAddress((void**)&pre1,     g_pre1);
    cudaGetSymbolAddress((void**)&dec_proj, g_dec_proj);
    cudaGetSymbolAddress((void**)&dec_in,   g_dec_in);
    cudaGetSymbolAddress((void**)&residual, g_residual);
    cudaGetSymbolAddress((void**)&pgi,      g_pgi);
    cudaGetSymbolAddress((void**)&pha,      g_pha);
    cudaGetSymbolAddress((void**)&ph1,      g_ph1);
    cudaGetSymbolAddress((void**)&ph2,      g_ph2);
    cudaGetSymbolAddress((void**)&psc,      g_psc);
    cudaGetSymbolAddress((void**)&ppx,      g_ppx);
    cudaGetSymbolAddress((void**)&pvec,     g_pvec);
    cudaGetSymbolAddress((void**)&psum,     g_psum);

    float* out       = (float*)d_out;                 // [64, 2, 80]
    float* h_att_out = out + Nn * Rr * Oo;            // [64, 1024]
    float* h_d1_out  = h_att_out + Nn * H2;
    float* h_d2_out  = h_d1_out + Nn * H2;

    // side stream for the hidden-state GEMMs (input-only deps)
    cudaStream_t s2;
    cudaStreamCreateWithFlags(&s2, cudaStreamNonBlocking);
    cudaEvent_t evF, evJ;
    cudaEventCreateWithFlags(&evF, cudaEventDisableTiming);
    cudaEventCreateWithFlags(&evJ, cudaEventDisableTiming);

    cudaEventRecord(evF, 0);
    cudaStreamWaitEvent(s2, evF, 0);
    // side: three Whh GEMMs (K=1024, SK=8 -> kc=128)
    launch3(mkgp(hidden_att,  H2, Whh_att, pha, H2, 8, G3),
            mkgp(hidden_dec1, H2, Whh_d1,  ph1, H2, 8, G3),
            mkgp(hidden_dec2, H2, Whh_d2,  ph2, H2, 8, G3), s2);
    cudaEventRecord(evJ, s2);

    // main: pre1 (K=80, direct bias+relu)
    launch1(mkgp(input_dec, Oo, W_pre1, pre1, Oo, 1, H2, b_pre1, 2));
    // main: pre2 partials (K=1024, SK=16 -> kc=64)
    launch1(mkgp(pre1, H2, W_pre2, ppx, H2, 16, Hh));
    // main: gi_att (K=512, SK=8 -> kc=64) with FUSED pre2 reduce (+bias+relu) in X staging
    launch1(mkgp(ppx, Hh, Wih_att, pgi, Hh, 8, G3, nullptr, 0, 16, b_pre2, 1));

    cudaStreamWaitEvent(0, evJ, 0);
    // D: attention GRU -> h_att + dec_in[:, H2:]
    gru_k<<<(Nn * H2) / 256, 256>>>(pgi, 8, pha, 8, bih_att, bhh_att, hidden_att,
                                    h_att_out, dec_in, nullptr, 0, nullptr,
                                    nullptr, nullptr);
    // E: dec_proj (K=1024, SK=16 -> kc=64)
    launch1(mkgp(h_att_out, H2, W_ld, ppx, H2, 16, H2));
    reduce_k<<<(Nn * H2) / 256, 256>>>(ppx, dec_proj, b_ld, H2, 16, 0);
    // F: fused attention
    {
        dim3 ga(ASPLIT, Nn);
        attn_fused_k<<<ga, 256>>>(input_enc, input_attW_enc, dec_proj,
                                  W_attn, b_attn, lengths_enc, pvec, psum);
    }
    attn_reduce2_k<<<Nn, 256>>>(pvec, psum, dec_in);
    // G: W_sc + gi_d1 (K=2048, SK=16 -> kc=128)
    launch2(mkgp(dec_in, 2 * H2, W_sc,   psc, 2 * H2, 16, H2),
            mkgp(dec_in, 2 * H2, Wih_d1, pgi, 2 * H2, 16, G3));
    // H: gru1 (fused W_sc reduce + residual)
    gru_k<<<(Nn * H2) / 256, 256>>>(pgi, 16, ph1, 8, bih_d1, bhh_d1, hidden_dec1,
                                    h_d1_out, nullptr, psc, 16, b_sc,
                                    nullptr, residual);
    // I: gi_d2 (K=1024, SK=16 -> kc=64, 768 blocks)
    launch1(mkgp(residual, H2, Wih_d2, pgi, H2, 16, G3));
    // J: gru2 (residual += h)
    gru_k<<<(Nn * H2) / 256, 256>>>(pgi, 16, ph2, 8, bih_d2, bhh_d2, hidden_dec2,
                                    h_d2_out, nullptr, nullptr, 0, nullptr,
                                    residual, residual);
    // K: output projection [64,160] (K=1024, SK=16 -> kc=64)
    launch1(mkgp(residual, H2, W_out, ppx, H2, 16, Rr * Oo));
    reduce_k<<<(Nn * Rr * Oo) / 256, 256>>>(ppx, out, b_out, Rr * Oo, 16, 0);
}

// round 12
// speedup vs baseline: 1.0706x; 1.0706x over previous
#include <cuda_runtime.h>
#include <math.h>

typedef unsigned long long ull;

#define Nn 64
#define Tt 800
#define Hh 512
#define H2 1024
#define G3 3072
#define Oo 80
#define Rr 2
#define ASPLIT 25
#define TSLICE 32

// ---------------- scratch (device globals; no allocation) ----------------
__device__ float g_pre1[Nn * H2];
__device__ float g_pre2[Nn * Hh];
__device__ float g_dec_proj[Nn * H2];
__device__ float g_dec_in[Nn * 2 * H2];
__device__ float g_residual[Nn * H2];
__device__ float g_pgi[16 * Nn * G3];
__device__ float g_pha[8 * Nn * G3];
__device__ float g_ph1[8 * Nn * G3];
__device__ float g_ph2[8 * Nn * G3];
__device__ float g_psc[16 * Nn * H2];
__device__ float g_ppx[16 * Nn * H2];
__device__ float g_pvec[ASPLIT * Nn * H2];
__device__ float g_psum[ASPLIT * Nn];

// ---------------- batched split-K skinny GEMM (v5) ---------------------------
// Tile 64 rows x 64 cols; thread = 4 rows x 4 strided cols, f32x2 over k.
// W chunks double-buffered in smem (1 bar/chunk, reg-prefetch) for KC<=80;
// classic 2-bar path for KC=128 (smem budget).
struct GP {
    const float* X; const float* W; float* P; const float* bias;
    int ldx; int K; int SK; int M; int cb; int fuse;  // fuse: 2 = bias+relu direct (SK==1)
};

__device__ __forceinline__ void ffma2(ull& d, ull a, ull b)
{
    asm("fma.rn.f32x2 %0, %1, %2, %0;" : "+l"(d) : "l"(a), "l"(b));
}

__device__ __forceinline__ float fast_tanh(float x)
{
    float y;
    asm("tanh.approx.f32 %0, %1;" : "=f"(y) : "f"(x));
    return y;
}

template<int KC>
__device__ __forceinline__ void gemm_tile(const GP& p, int colb, int sp, char* raw)
{
    constexpr int  LDSX = (KC == 128) ? 132 : (KC + 4);
    constexpr bool PP   = (KC <= 80);
    constexpr int  WBUF = 64 * 36;

    float* sx = (float*)raw;
    float* ws = sx + 64 * LDSX;

    const int kbeg = sp * KC;
    const int tid  = threadIdx.x;

    {   // stage X[0:64][kbeg:kbeg+KC]
        const int r = tid >> 2, q = (tid & 3) * 4;
        float* sr = sx + r * LDSX;
        const float* xp = p.X + (size_t)r * p.ldx + kbeg + q;
#pragma unroll
        for (int kk = 0; kk < KC; kk += 16)
            *(float4*)&sr[kk + q] = *(const float4*)&xp[kk];
    }

    // W loader mapping: thread covers (wcol, wcol+32) x 16B segment wseg
    const int wcol = tid >> 3;
    const int wseg = (tid & 7) * 4;
    int gc0 = colb * 64 + wcol;      if (gc0 >= p.M) gc0 = 0;
    int gc1 = colb * 64 + wcol + 32; if (gc1 >= p.M) gc1 = 0;
    const float* wg0 = p.W + (size_t)gc0 * p.K + kbeg + wseg;
    const float* wg1 = p.W + (size_t)gc1 * p.K + kbeg + wseg;

    constexpr int CS0 = KC < 32 ? KC : 32;
    float4 pf0 = make_float4(0.f, 0.f, 0.f, 0.f), pf1 = pf0;
    if (wseg < CS0) { pf0 = *(const float4*)wg0; pf1 = *(const float4*)wg1; }

    ull acc[4][4];
#pragma unroll
    for (int cc = 0; cc < 4; cc++)
#pragma unroll
        for (int r = 0; r < 4; r++) acc[cc][r] = 0ull;

    const int cg    = tid & 15;          // cols {cg, cg+16, cg+32, cg+48}
    const int rbase = (tid >> 4) * 4;    // rows rbase..rbase+3

    constexpr int NCH = (KC + 31) / 32;
#pragma unroll
    for (int ch = 0; ch < NCH; ch++) {
        const int k0 = ch * 32;
        const int cs = (KC - k0) < 32 ? (KC - k0) : 32;
        float* wb = PP ? (ws + (ch & 1) * WBUF) : ws;
        if (!PP) __syncthreads();
        *(float4*)&wb[wcol * 36 + wseg]        = pf0;
        *(float4*)&wb[(wcol + 32) * 36 + wseg] = pf1;
        __syncthreads();
        if (ch + 1 < NCH) {
            const int nk = (ch + 1) * 32;
            const int cs2 = (KC - nk) < 32 ? (KC - nk) : 32;
            if (wseg < cs2) {
                pf0 = *(const float4*)(wg0 + nk);
                pf1 = *(const float4*)(wg1 + nk);
            }
        }
        const float* xb = sx + rbase * LDSX + k0;
        const int nkp = cs >> 2;
#pragma unroll
        for (int kp = 0; kp < 8; kp++) {
            if (kp < nkp) {
                ulonglong2 xv[4], wv[4];
#pragma unroll
                for (int r = 0; r < 4; r++)
                    xv[r] = *(const ulonglong2*)(xb + r * LDSX + kp * 4);
#pragma unroll
                for (int cc = 0; cc < 4; cc++)
                    wv[cc] = *(const ulonglong2*)(wb + (cg + 16 * cc) * 36 + kp * 4);
#pragma unroll
                for (int cc = 0; cc < 4; cc++)
#pragma unroll
                    for (int r = 0; r < 4; r++) {
                        ffma2(acc[cc][r], xv[r].x, wv[cc].x);
                        ffma2(acc[cc][r], xv[r].y, wv[cc].y);
                    }
            }
        }
    }

    // epilogue: horizontal add + store (col-guarded)
#pragma unroll
    for (int cc = 0; cc < 4; cc++) {
        const int col = colb * 64 + cg + 16 * cc;
        if (col < p.M) {
#pragma unroll
            for (int r = 0; r < 4; r++) {
                float v = __uint_as_float((unsigned)(acc[cc][r] & 0xffffffffull)) +
                          __uint_as_float((unsigned)(acc[cc][r] >> 32));
                if (p.fuse) {
                    v += p.bias[col];
                    if (p.fuse == 2) v = fmaxf(v, 0.f);
                    p.P[(size_t)(rbase + r) * p.M + col] = v;
                } else {
                    p.P[(size_t)(sp * 64 + rbase + r) * p.M + col] = v;
                }
            }
        }
    }
}

__global__ void __launch_bounds__(256, 2) gemm_sk(GP p0, GP p1, GP p2, GP p3,
                                                  int n0, int n1, int n2)
{
    __shared__ __align__(16) char raw[43008];
    GP p; int lb;
    {
        const int bid = blockIdx.x;
        if (bid < n0)      { p = p0; lb = bid; }
        else if (bid < n1) { p = p1; lb = bid - n0; }
        else if (bid < n2) { p = p2; lb = bid - n1; }
        else               { p = p3; lb = bid - n2; }
    }
    const int colb = lb % p.cb;
    const int sp   = lb / p.cb;
    const int kc   = p.K / p.SK;          // 64, 80, or 128

    if (kc == 64)       gemm_tile<64>(p, colb, sp, raw);
    else if (kc == 128) gemm_tile<128>(p, colb, sp, raw);
    else                gemm_tile<80>(p, colb, sp, raw);
}

// ---------------- standalone partial reduce: out = sum(P) + bias (opt relu) ----------------
__global__ void reduce_k(const float* __restrict__ P, float* __restrict__ out,
                         const float* __restrict__ bias, int M, int SK, int relu)
{
    const int idx = blockIdx.x * 256 + threadIdx.x;
    const int r = idx / M, col = idx % M;
    float s = bias[col];
    for (int sp = 0; sp < SK; sp++) s += P[((size_t)(sp * 64 + r)) * M + col];
    if (relu) s = fmaxf(s, 0.f);
    out[(size_t)r * M + col] = s;
}

// ---------------- GRU combine with fused split-K reduce ----------------
__global__ void gru_k(const float* __restrict__ giP, int skGi,
                      const float* __restrict__ ghP, int skGh,
                      const float* __restrict__ bih, const float* __restrict__ bhh,
                      const float* __restrict__ hprev,
                      float* __restrict__ hout, float* __restrict__ hout2,
                      const float* __restrict__ scP, int skSc,
                      const float* __restrict__ b_sc,
                      const float* __restrict__ resin, float* __restrict__ resout)
{
    const int idx = blockIdx.x * 256 + threadIdx.x;    // 0..65535
    const int n = idx >> 10, h = idx & (H2 - 1);
    float ir = bih[h], iz = bih[h + H2], inn = bih[h + 2 * H2];
    for (int sp = 0; sp < skGi; sp++) {
        const size_t b = ((size_t)(sp * 64 + n)) * G3 + h;
        ir += giP[b]; iz += giP[b + H2]; inn += giP[b + 2 * H2];
    }
    float hr = bhh[h], hz = bhh[h + H2], hn = bhh[h + 2 * H2];
    for (int sp = 0; sp < skGh; sp++) {
        const size_t b = ((size_t)(sp * 64 + n)) * G3 + h;
        hr += ghP[b]; hz += ghP[b + H2]; hn += ghP[b + 2 * H2];
    }
    const float r  = 1.f / (1.f + __expf(-(ir + hr)));
    const float z  = 1.f / (1.f + __expf(-(iz + hz)));
    const float nn = fast_tanh(inn + r * hn);
    const float hp = hprev[(size_t)n * H2 + h];
    const float hv = (1.f - z) * nn + z * hp;
    hout[(size_t)n * H2 + h] = hv;
    if (hout2) hout2[(size_t)n * 2 * H2 + H2 + h] = hv;
    if (scP) {
        float rv = b_sc[h];
        for (int sp = 0; sp < skSc; sp++)
            rv += scP[((size_t)(sp * 64 + n)) * H2 + h];
        resout[(size_t)n * H2 + h] = rv + hv;
    } else if (resin) {
        resout[(size_t)n * H2 + h] = resin[(size_t)n * H2 + h] + hv;
    }
}

// ---------------- fused attention: scores + unnormalized weighted sum ----------------
__global__ void attn_fused_k(const float* __restrict__ enc,
                             const float* __restrict__ attW,
                             const float* __restrict__ dec_proj,
                             const float* __restrict__ Wattn,
                             const float* __restrict__ b_attn,
                             const int* __restrict__ lengths,
                             float* __restrict__ pvec,
                             float* __restrict__ psum)
{
    __shared__ float dp[H2];
    __shared__ float wa[H2];
    __shared__ float sc[TSLICE];
    __shared__ float wsum[8];
    const int n = blockIdx.y, sp = blockIdx.x;
    const int tid = threadIdx.x;
    {
        const int h = tid * 4;
        *(float4*)&dp[h] = *(const float4*)&dec_proj[(size_t)n * H2 + h];
        *(float4*)&wa[h] = *(const float4*)&Wattn[h];
    }
    const int t0  = sp * TSLICE;
    const int len = lengths[n];
    int eff = len - t0;
    if (eff > TSLICE) eff = TSLICE;
    if (eff < 0) eff = 0;
    __syncthreads();

    // phase 1: scores (warp per timestep), HW tanh
    const int warp = tid >> 5, lane = tid & 31;
    float wls = 0.f;
    for (int tl = warp; tl < eff; tl += 8) {
        const float* a = attW + ((size_t)n * Tt + t0 + tl) * H2;
        float s = 0.f;
#pragma unroll
        for (int i = 0; i < 8; i++) {
            const int h = i * 128 + lane * 4;
            float4 v = *(const float4*)&a[h];
            s += fast_tanh(v.x + dp[h + 0]) * wa[h + 0];
            s += fast_tanh(v.y + dp[h + 1]) * wa[h + 1];
            s += fast_tanh(v.z + dp[h + 2]) * wa[h + 2];
            s += fast_tanh(v.w + dp[h + 3]) * wa[h + 3];
        }
#pragma unroll
        for (int o = 16; o > 0; o >>= 1) s += __shfl_xor_sync(0xffffffffu, s, o);
        s = __expf(s + b_attn[0]);
        if (lane == 0) sc[tl] = s;
        wls += s;
    }
    if (lane == 0) wsum[warp] = wls;
    __syncthreads();

    if (tid == 0) {
        float tot = 0.f;
#pragma unroll
        for (int w = 0; w < 8; w++) tot += wsum[w];
        psum[(size_t)sp * Nn + n] = tot;
    }

    // phase 2: unnormalized weighted sum over this slice
    const int h = tid * 4;
    float4 acc = make_float4(0.f, 0.f, 0.f, 0.f);
    const float* ep = enc + ((size_t)n * Tt + t0) * H2 + h;
#pragma unroll 2
    for (int tl = 0; tl < eff; tl++) {
        const float w = sc[tl];
        float4 v = *(const float4*)(ep + (size_t)tl * H2);
        acc.x = fmaf(w, v.x, acc.x);
        acc.y = fmaf(w, v.y, acc.y);
        acc.z = fmaf(w, v.z, acc.z);
        acc.w = fmaf(w, v.w, acc.w);
    }
    *(float4*)&pvec[((size_t)sp * Nn + n) * H2 + h] = acc;
}

// ---------------- attention final reduce: normalize + write dec_in[:, :H2] ----------------
__global__ void attn_reduce2_k(const float* __restrict__ pvec,
                               const float* __restrict__ psum,
                               float* __restrict__ dec_in)
{
    const int n = blockIdx.x;
    __shared__ float ps[ASPLIT];
    if (threadIdx.x < ASPLIT) ps[threadIdx.x] = psum[(size_t)threadIdx.x * Nn + n];
    __syncthreads();
    float den = 0.f;
#pragma unroll
    for (int sp = 0; sp < ASPLIT; sp++) den += ps[sp];
    const float inv = 1.f / fmaxf(den, 1e-12f);
    const int h = threadIdx.x * 4;
    float4 acc = make_float4(0.f, 0.f, 0.f, 0.f);
#pragma unroll
    for (int sp = 0; sp < ASPLIT; sp++) {
        float4 v = *(const float4*)&pvec[((size_t)sp * Nn + n) * H2 + h];
        acc.x += v.x; acc.y += v.y; acc.z += v.z; acc.w += v.w;
    }
    acc.x *= inv; acc.y *= inv; acc.z *= inv; acc.w *= inv;
    *(float4*)&dec_in[(size_t)n * 2 * H2 + h] = acc;
}

// ---------------- host-side orchestration ----------------
static inline GP mkgp(const float* X, int ldx, const float* W, float* P,
                      int K, int SK, int M, const float* bias = nullptr, int fuse = 0)
{
    GP g; g.X = X; g.ldx = ldx; g.W = W; g.P = P; g.bias = bias;
    g.K = K; g.SK = SK; g.M = M; g.cb = (M + 63) / 64; g.fuse = fuse; return g;
}
static inline int nblk(const GP& g) { return g.cb * g.SK; }

static inline void launch1(const GP& a, cudaStream_t st = 0) {
    int n = nblk(a);
    gemm_sk<<<n, 256, 0, st>>>(a, a, a, a, n, n, n);
}
static inline void launch2(const GP& a, const GP& b, cudaStream_t st = 0) {
    int na = nblk(a), nb = nblk(b);
    gemm_sk<<<na + nb, 256, 0, st>>>(a, b, b, b, na, na + nb, na + nb);
}
static inline void launch3(const GP& a, const GP& b, const GP& c, cudaStream_t st = 0) {
    int na = nblk(a), nb = nblk(b), nc = nblk(c);
    gemm_sk<<<na + nb + nc, 256, 0, st>>>(a, b, c, c, na, na + nb, na + nb + nc);
}

extern "C" void kernel_launch(void* const* d_in, const int* in_sizes, int n_in,
                              void* d_out, int out_size)
{
    const float* input_enc      = (const float*)d_in[0];
    const float* input_attW_enc = (const float*)d_in[1];
    const float* input_dec      = (const float*)d_in[2];
    const int*   lengths_enc    = (const int*)  d_in[3];
    const float* hidden_att     = (const float*)d_in[4];
    const float* hidden_dec1    = (const float*)d_in[5];
    const float* hidden_dec2    = (const float*)d_in[6];
    const float* W_pre1 = (const float*)d_in[7];
    const float* b_pre1 = (const float*)d_in[8];
    const float* W_pre2 = (const float*)d_in[9];
    const float* b_pre2 = (const float*)d_in[10];
    const float* Wih_att = (const float*)d_in[11];
    const float* Whh_att = (const float*)d_in[12];
    const float* bih_att = (const float*)d_in[13];
    const float* bhh_att = (const float*)d_in[14];
    const float* W_ld   = (const float*)d_in[15];
    const float* b_ld   = (const float*)d_in[16];
    const float* W_attn = (const float*)d_in[17];
    const float* b_attn = (const float*)d_in[18];
    const float* W_sc   = (const float*)d_in[19];
    const float* b_sc   = (const float*)d_in[20];
    const float* Wih_d1 = (const float*)d_in[21];
    const float* Whh_d1 = (const float*)d_in[22];
    const float* bih_d1 = (const float*)d_in[23];
    const float* bhh_d1 = (const float*)d_in[24];
    const float* Wih_d2 = (const float*)d_in[25];
    const float* Whh_d2 = (const float*)d_in[26];
    const float* bih_d2 = (const float*)d_in[27];
    const float* bhh_d2 = (const float*)d_in[28];
    const float* W_out  = (const float*)d_in[29];
    const float* b_out  = (const float*)d_in[30];

    float *pre1, *pre2, *dec_proj, *dec_in, *residual;
    float *pgi, *pha, *ph1, *ph2, *psc, *ppx, *pvec, *psum;
    cudaGetSymbolAddress((void**)&pre1,     g_pre1);
    cudaGetSymbolAddress((void**)&pre2,     g_pre2);
    cudaGetSymbolAddress((void**)&dec_proj, g_dec_proj);
    cudaGetSymbolAddress((void**)&dec_in,   g_dec_in);
    cudaGetSymbolAddress((void**)&residual, g_residual);
    cudaGetSymbolAddress((void**)&pgi,      g_pgi);
    cudaGetSymbolAddress((void**)&pha,      g_pha);
    cudaGetSymbolAddress((void**)&ph1,      g_ph1);
    cudaGetSymbolAddress((void**)&ph2,      g_ph2);
    cudaGetSymbolAddress((void**)&psc,      g_psc);
    cudaGetSymbolAddress((void**)&ppx,      g_ppx);
    cudaGetSymbolAddress((void**)&pvec,     g_pvec);
    cudaGetSymbolAddress((void**)&psum,     g_psum);

    float* out       = (float*)d_out;                 // [64, 2, 80]
    float* h_att_out = out + Nn * Rr * Oo;            // [64, 1024]
    float* h_d1_out  = h_att_out + Nn * H2;
    float* h_d2_out  = h_d1_out + Nn * H2;

    // side stream for the hidden-state GEMMs (input-only deps)
    cudaStream_t s2;
    cudaStreamCreateWithFlags(&s2, cudaStreamNonBlocking);
    cudaEvent_t evF, evJ;
    cudaEventCreateWithFlags(&evF, cudaEventDisableTiming);
    cudaEventCreateWithFlags(&evJ, cudaEventDisableTiming);

    cudaEventRecord(evF, 0);
    cudaStreamWaitEvent(s2, evF, 0);
    // side: three Whh GEMMs (K=1024, SK=8 -> kc=128)
    launch3(mkgp(hidden_att,  H2, Whh_att, pha, H2, 8, G3),
            mkgp(hidden_dec1, H2, Whh_d1,  ph1, H2, 8, G3),
            mkgp(hidden_dec2, H2, Whh_d2,  ph2, H2, 8, G3), s2);
    cudaEventRecord(evJ, s2);

    // main: pre1 (K=80, direct bias+relu)
    launch1(mkgp(input_dec, Oo, W_pre1, pre1, Oo, 1, H2, b_pre1, 2));
    // main: pre2 partials (K=1024, SK=16 -> kc=64) + standalone reduce
    launch1(mkgp(pre1, H2, W_pre2, ppx, H2, 16, Hh));
    reduce_k<<<(Nn * Hh) / 256, 256>>>(ppx, pre2, b_pre2, Hh, 16, 1);
    // main: gi_att (K=512, SK=8 -> kc=64)
    launch1(mkgp(pre2, Hh, Wih_att, pgi, Hh, 8, G3));

    cudaStreamWaitEvent(0, evJ, 0);
    // D: attention GRU -> h_att + dec_in[:, H2:]
    gru_k<<<(Nn * H2) / 256, 256>>>(pgi, 8, pha, 8, bih_att, bhh_att, hidden_att,
                                    h_att_out, dec_in, nullptr, 0, nullptr,
                                    nullptr, nullptr);
    // E: dec_proj (K=1024, SK=16 -> kc=64)
    launch1(mkgp(h_att_out, H2, W_ld, ppx, H2, 16, H2));
    reduce_k<<<(Nn * H2) / 256, 256>>>(ppx, dec_proj, b_ld, H2, 16, 0);
    // F: fused attention
    {
        dim3 ga(ASPLIT, Nn);
        attn_fused_k<<<ga, 256>>>(input_enc, input_attW_enc, dec_proj,
                                  W_attn, b_attn, lengths_enc, pvec, psum);
    }
    attn_reduce2_k<<<Nn, 256>>>(pvec, psum, dec_in);
    // G: W_sc + gi_d1 (K=2048, SK=16 -> kc=128)
    launch2(mkgp(dec_in, 2 * H2, W_sc,   psc, 2 * H2, 16, H2),
            mkgp(dec_in, 2 * H2, Wih_d1, pgi, 2 * H2, 16, G3));
    // H: gru1 (fused W_sc reduce + residual)
    gru_k<<<(Nn * H2) / 256, 256>>>(pgi, 16, ph1, 8, bih_d1, bhh_d1, hidden_dec1,
                                    h_d1_out, nullptr, psc, 16, b_sc,
                                    nullptr, residual);
    // I: gi_d2 (K=1024, SK=16 -> kc=64, 768 blocks)
    launch1(mkgp(residual, H2, Wih_d2, pgi, H2, 16, G3));
    // J: gru2 (residual += h)
    gru_k<<<(Nn * H2) / 256, 256>>>(pgi, 16, ph2, 8, bih_d2, bhh_d2, hidden_dec2,
                                    h_d2_out, nullptr, nullptr, 0, nullptr,
                                    residual, residual);
    // K: output projection [64,160] (K=1024, SK=16 -> kc=64)
    launch1(mkgp(residual, H2, W_out, ppx, H2, 16, Rr * Oo));
    reduce_k<<<(Nn * Rr * Oo) / 256, 256>>>(ppx, out, b_out, Rr * Oo, 16, 0);
}